// round 3
// baseline (speedup 1.0000x reference)
#include <cuda_runtime.h>
#include <cstdint>

// ---------------------------------------------------------------------------
// VectorQuantization (VQ-VAE EMA), B=64, C=64, H=64, W=64, K=512
// R3: R2 retile + alignment fixes (odd OFF_IND scalar stores; __align__(16)
//     on all vector-accessed device/shared arrays).
// ---------------------------------------------------------------------------

#define N_PTS   262144
#define CDIM    64
#define KCODES  512
#define HWSZ    4096

#define OFF_OUT   0
#define OFF_DIFF  16777216
#define OFF_IND   16777217
#define OFF_EMB   17039361
#define OFF_NCS   17072129
#define OFF_AVG   17072641

// ------------------------- device scratch ----------------------------------
__device__ __align__(16) float g_e2[KCODES];
__device__ __align__(16) int   g_ind[N_PTS];
__device__ __align__(16) float g_counts[KCODES];
__device__ __align__(16) float g_embsumT[KCODES * CDIM];   // [k][c]
__device__ __align__(16) float g_cs[KCODES];
__device__ float g_diff;

// ------------------------- helpers -----------------------------------------
__device__ __forceinline__ unsigned long long fma2(unsigned long long a,
                                                   unsigned long long b,
                                                   unsigned long long c) {
    unsigned long long d;
    asm("fma.rn.f32x2 %0, %1, %2, %3;" : "=l"(d) : "l"(a), "l"(b), "l"(c));
    return d;
}
__device__ __forceinline__ unsigned long long dup2(float x) {
    unsigned long long r;
    unsigned int xi = __float_as_uint(x);
    asm("mov.b64 %0, {%1, %1};" : "=l"(r) : "r"(xi));
    return r;
}
__device__ __forceinline__ void unpack2(unsigned long long v, float& lo, float& hi) {
    unsigned int a, b;
    asm("mov.b64 {%0, %1}, %2;" : "=r"(a), "=r"(b) : "l"(v));
    lo = __uint_as_float(a);
    hi = __uint_as_float(b);
}
__device__ __forceinline__ void red4(float* p, float a, float b, float c, float d) {
    unsigned long long g = (unsigned long long)__cvta_generic_to_global(p);
    asm volatile("red.global.add.v4.f32 [%0], {%1,%2,%3,%4};"
                 :: "l"(g), "f"(a), "f"(b), "f"(c), "f"(d) : "memory");
}
__device__ __forceinline__ void red1(float* p, float a) {
    unsigned long long g = (unsigned long long)__cvta_generic_to_global(p);
    asm volatile("red.global.add.f32 [%0], %1;" :: "l"(g), "f"(a) : "memory");
}

// ------------------------- kernel 0: init ----------------------------------
__global__ void k_init(const float* __restrict__ emb) {
    int b = blockIdx.x, t = threadIdx.x;
    if (b < 64) {
        g_embsumT[b * 512 + t] = 0.0f;
    } else {
        g_counts[t] = 0.0f;
        float s = 0.0f;
        for (int c = 0; c < CDIM; c++) {
            float v = emb[c * KCODES + t];
            s = __fadd_rn(s, __fmul_rn(v, v));
        }
        g_e2[t] = s;
        if (t == 0) g_diff = 0.0f;
    }
}

// ------------------------- kernel 1: argmin GEMM ---------------------------
// Block 256 thr / 64 points. warp w -> points [8w,8w+8); lane owns codes
// {kb + lane + 32j, j=0..7}. acc: 8 points (4 f32x2) x 8 codes.
__global__ void __launch_bounds__(256, 2) k_argmin(const float* __restrict__ in,
                                                   const float* __restrict__ emb) {
    __shared__ __align__(16) float As[64 * 64];    // [c][p]
    __shared__ __align__(16) float Bs[32 * 256];   // [c][j]

    const int tid  = threadIdx.x;
    const int warp = tid >> 5;
    const int lane = tid & 31;
    const int wp8  = warp << 3;
    const int n0   = blockIdx.x * 64;
    const int b    = n0 >> 12;
    const int hw0  = n0 & 4095;
    const float* inb = in + (size_t)b * CDIM * HWSZ + hw0;

    for (int idx = tid; idx < 64 * 16; idx += 256) {
        int c = idx >> 4, p4 = (idx & 15) << 2;
        *(float4*)&As[c * 64 + p4] = *(const float4*)(inb + (size_t)c * HWSZ + p4);
    }
    __syncthreads();

    float x2[8];
#pragma unroll
    for (int p = 0; p < 8; p++) {
        float s = 0.0f;
        for (int c = 0; c < CDIM; c++) {
            float v = As[c * 64 + wp8 + p];
            s = __fadd_rn(s, __fmul_rn(v, v));
        }
        x2[p] = s;
    }

    float best[8];
    int   bk[8];
#pragma unroll
    for (int p = 0; p < 8; p++) { best[p] = 3.4e38f; bk[p] = 0; }

    for (int kb = 0; kb < KCODES; kb += 256) {
        unsigned long long acc[4][8];
#pragma unroll
        for (int i = 0; i < 4; i++)
#pragma unroll
            for (int j = 0; j < 8; j++) acc[i][j] = 0ull;

        for (int ch = 0; ch < 64; ch += 32) {
            __syncthreads();
            for (int idx = tid; idx < 32 * 64; idx += 256) {
                int c = idx >> 6, j4 = (idx & 63) << 2;
                *(float4*)&Bs[c * 256 + j4] =
                    *(const float4*)(emb + (ch + c) * KCODES + kb + j4);
            }
            __syncthreads();

#pragma unroll 4
            for (int cc = 0; cc < 32; cc++) {
                ulonglong2 A0 = *(const ulonglong2*)&As[(ch + cc) * 64 + wp8];
                ulonglong2 A1 = *(const ulonglong2*)&As[(ch + cc) * 64 + wp8 + 4];
#pragma unroll
                for (int j = 0; j < 8; j++) {
                    unsigned long long Bv = dup2(Bs[cc * 256 + lane + 32 * j]);
                    acc[0][j] = fma2(A0.x, Bv, acc[0][j]);
                    acc[1][j] = fma2(A0.y, Bv, acc[1][j]);
                    acc[2][j] = fma2(A1.x, Bv, acc[2][j]);
                    acc[3][j] = fma2(A1.y, Bv, acc[3][j]);
                }
            }
        }

        // epilogue: dist = (x2 - 2*dot) + e2; k ascending within thread
#pragma unroll
        for (int j = 0; j < 8; j++) {
            int k = kb + lane + 32 * j;
            float e2 = __ldg(&g_e2[k]);
#pragma unroll
            for (int pp = 0; pp < 4; pp++) {
                float dlo, dhi;
                unpack2(acc[pp][j], dlo, dhi);
                int p0 = pp * 2, p1 = pp * 2 + 1;
                float v0 = __fadd_rn(__fsub_rn(x2[p0], __fmul_rn(2.0f, dlo)), e2);
                float v1 = __fadd_rn(__fsub_rn(x2[p1], __fmul_rn(2.0f, dhi)), e2);
                if (v0 < best[p0]) { best[p0] = v0; bk[p0] = k; }
                if (v1 < best[p1]) { best[p1] = v1; bk[p1] = k; }
            }
        }
    }

    // cross-lane reduce, first-index tie-break (matches jnp.argmin)
#pragma unroll
    for (int off = 16; off > 0; off >>= 1) {
#pragma unroll
        for (int p = 0; p < 8; p++) {
            float od = __shfl_down_sync(0xffffffffu, best[p], off);
            int   ok = __shfl_down_sync(0xffffffffu, bk[p], off);
            if (od < best[p] || (od == best[p] && ok < bk[p])) {
                best[p] = od; bk[p] = ok;
            }
        }
    }
    if (lane == 0) {
#pragma unroll
        for (int p = 0; p < 8; p++) g_ind[n0 + wp8 + p] = bk[p];
    }
}

// ------------------------- kernel 2: apply ---------------------------------
// 512 blocks x 256 thr; block = 512 points (2/thread), channels in 4 groups
// of 16 (32KB embS). embedding_sum via red.global.v4 into g_embsumT[k][c].
__global__ void __launch_bounds__(256) k_apply(const float* __restrict__ in,
                                               const float* __restrict__ emb,
                                               float* __restrict__ outp) {
    __shared__ __align__(16) float embS[16 * KCODES];
    __shared__ float cntS[KCODES];
    __shared__ float red[8];

    const int tid  = threadIdx.x;
    const int base = blockIdx.x * 512;
    const int b    = base >> 12;
    const int hw   = (base & 4095) + 2 * tid;
    const int p0   = base + 2 * tid;

    cntS[tid] = 0.0f;
    cntS[tid + 256] = 0.0f;

    const int2 kk = *(const int2*)&g_ind[p0];   // g_ind 16B-aligned, p0 even
    float dacc = 0.0f;

    for (int cg = 0; cg < 4; cg++) {
        __syncthreads();
        for (int idx = tid; idx < 16 * 128; idx += 256) {
            int c = idx >> 7, j4 = (idx & 127) << 2;
            *(float4*)&embS[c * KCODES + j4] =
                *(const float4*)(emb + (cg * 16 + c) * KCODES + j4);
        }
        __syncthreads();

#pragma unroll
        for (int q = 0; q < 4; q++) {
            float2 xv[4];
#pragma unroll
            for (int cc = 0; cc < 4; cc++) {
                int c = cg * 16 + q * 4 + cc;
                size_t ib = ((size_t)(b * 64 + c)) * HWSZ + hw;
                float2 x = *(const float2*)&in[ib];
                float e0 = embS[(q * 4 + cc) * KCODES + kk.x];
                float e1 = embS[(q * 4 + cc) * KCODES + kk.y];
                float d0 = __fsub_rn(e0, x.x);
                float d1 = __fsub_rn(e1, x.y);
                float2 o = make_float2(__fadd_rn(x.x, d0), __fadd_rn(x.y, d1));
                *(float2*)&outp[OFF_OUT + ib] = o;
                dacc = __fadd_rn(dacc, __fmul_rn(d0, d0));
                dacc = __fadd_rn(dacc, __fmul_rn(d1, d1));
                xv[cc] = x;
            }
            red4(&g_embsumT[kk.x * 64 + cg * 16 + q * 4],
                 xv[0].x, xv[1].x, xv[2].x, xv[3].x);
            red4(&g_embsumT[kk.y * 64 + cg * 16 + q * 4],
                 xv[0].y, xv[1].y, xv[2].y, xv[3].y);
        }
    }

    // counts + ind (OFF_IND is odd -> scalar stores only)
    atomicAdd(&cntS[kk.x], 1.0f);
    atomicAdd(&cntS[kk.y], 1.0f);
    outp[OFF_IND + p0]     = (float)kk.x;
    outp[OFF_IND + p0 + 1] = (float)kk.y;
    __syncthreads();

    float v0 = cntS[tid], v1 = cntS[tid + 256];
    if (v0 != 0.0f) red1(&g_counts[tid], v0);
    if (v1 != 0.0f) red1(&g_counts[tid + 256], v1);

#pragma unroll
    for (int off = 16; off > 0; off >>= 1)
        dacc += __shfl_down_sync(0xffffffffu, dacc, off);
    if ((tid & 31) == 0) red[tid >> 5] = dacc;
    __syncthreads();
    if (tid == 0) {
        float s = 0.0f;
#pragma unroll
        for (int w = 0; w < 8; w++) s += red[w];
        red1(&g_diff, s);
    }
}

// ------------------------- kernel 3a: finalize (small) ---------------------
__global__ void k_final1(const float* __restrict__ csin,
                         float* __restrict__ outp) {
    __shared__ float redS[512];
    int k = threadIdx.x;
    float ncs = __fadd_rn(__fmul_rn(csin[k], 0.99f), __fmul_rn(0.01f, g_counts[k]));
    outp[OFF_NCS + k] = ncs;
    redS[k] = ncs;
    __syncthreads();
    for (int s = 256; s > 0; s >>= 1) {
        if (k < s) redS[k] += redS[k + s];
        __syncthreads();
    }
    float n = redS[0];
    g_cs[k] = __fmul_rn(__fdiv_rn(__fadd_rn(ncs, 1e-5f),
                                  __fadd_rn(n, 512.0f * 1e-5f)), n);
    if (k == 0) outp[OFF_DIFF] = g_diff * (1.0f / 16777216.0f);
}

// ------------------------- kernel 3b: finalize (bulk) ----------------------
__global__ void k_final2(const float* __restrict__ avgin,
                         float* __restrict__ outp) {
    int idx = blockIdx.x * 512 + threadIdx.x;   // 64 x 512 = 32768
    int c = idx >> 9, k = idx & 511;
    float a = __fadd_rn(__fmul_rn(avgin[c * KCODES + k], 0.99f),
                        __fmul_rn(0.01f, g_embsumT[k * 64 + c]));
    outp[OFF_AVG + c * KCODES + k] = a;
    outp[OFF_EMB + c * KCODES + k] = __fdiv_rn(a, g_cs[k]);
}

// ------------------------- launcher ----------------------------------------
extern "C" void kernel_launch(void* const* d_in, const int* in_sizes, int n_in,
                              void* d_out, int out_size) {
    const float* input         = (const float*)d_in[0];
    const float* embedding     = (const float*)d_in[1];
    const float* cluster_size  = (const float*)d_in[2];
    const float* embedding_avg = (const float*)d_in[3];
    float* out = (float*)d_out;

    k_init<<<65, 512>>>(embedding);
    k_argmin<<<4096, 256>>>(input, embedding);
    k_apply<<<512, 256>>>(input, embedding, out);
    k_final1<<<1, 512>>>(cluster_size, out);
    k_final2<<<64, 512>>>(embedding_avg, out);
}

// round 6
// speedup vs baseline: 1.2875x; 1.2875x over previous
#include <cuda_runtime.h>
#include <cuda_bf16.h>
#include <cstdint>

// ---------------------------------------------------------------------------
// VectorQuantization (VQ-VAE EMA), B=64, C=64, H=64, W=64, K=512
// R6 (= R5 resubmit after infra failure): argmin via mma.sync bf16x6
// emulated-FP32 GEMM (sm_100-safe) + exact-fp32 refine for near-margin
// points. Apply/finals from R3 (proven).
// ---------------------------------------------------------------------------

#define N_PTS   262144
#define CDIM    64
#define KCODES  512
#define HWSZ    4096

#define OFF_OUT   0
#define OFF_DIFF  16777216
#define OFF_IND   16777217
#define OFF_EMB   17039361
#define OFF_NCS   17072129
#define OFF_AVG   17072641

#define MARGIN  1e-3f

// ------------------------- device scratch ----------------------------------
__device__ __align__(16) float g_e2[KCODES];
__device__ __align__(16) int   g_ind[N_PTS];
__device__ __align__(16) float g_counts[KCODES];
__device__ __align__(16) float g_embsumT[KCODES * CDIM];   // [k][c]
__device__ __align__(16) float g_cs[KCODES];
__device__ float g_diff;
__device__ int   g_nflag;
__device__ __align__(16) int g_flaglist[N_PTS];
// bf16 limb images of codebook, row-major [n][c], 128B rows
__device__ __align__(16) unsigned char g_bimg[3][KCODES * 128];

// ------------------------- helpers -----------------------------------------
__device__ __forceinline__ uint32_t s2u(const void* p) {
    uint32_t a;
    asm("{ .reg .u64 t; cvta.to.shared.u64 t, %1; cvt.u32.u64 %0, t; }"
        : "=r"(a) : "l"(p));
    return a;
}
__device__ __forceinline__ void red4(float* p, float a, float b, float c, float d) {
    unsigned long long g = (unsigned long long)__cvta_generic_to_global(p);
    asm volatile("red.global.add.v4.f32 [%0], {%1,%2,%3,%4};"
                 :: "l"(g), "f"(a), "f"(b), "f"(c), "f"(d) : "memory");
}
__device__ __forceinline__ void red1(float* p, float a) {
    unsigned long long g = (unsigned long long)__cvta_generic_to_global(p);
    asm volatile("red.global.add.f32 [%0], %1;" :: "l"(g), "f"(a) : "memory");
}
__device__ __forceinline__ void ldsm4(uint32_t& r0, uint32_t& r1,
                                      uint32_t& r2, uint32_t& r3, uint32_t addr) {
    asm volatile("ldmatrix.sync.aligned.m8n8.x4.shared.b16 {%0,%1,%2,%3}, [%4];"
                 : "=r"(r0), "=r"(r1), "=r"(r2), "=r"(r3) : "r"(addr));
}
__device__ __forceinline__ void mma16816(float* c, const uint32_t* a,
                                         uint32_t b0, uint32_t b1) {
    asm volatile("mma.sync.aligned.m16n8k16.row.col.f32.bf16.bf16.f32 "
                 "{%0,%1,%2,%3}, {%4,%5,%6,%7}, {%8,%9}, {%0,%1,%2,%3};"
                 : "+f"(c[0]), "+f"(c[1]), "+f"(c[2]), "+f"(c[3])
                 : "r"(a[0]), "r"(a[1]), "r"(a[2]), "r"(a[3]), "r"(b0), "r"(b1));
}

// ------------------------- kernel 0: init ----------------------------------
__global__ void k_init(const float* __restrict__ emb) {
    int b = blockIdx.x, t = threadIdx.x;
    if (b < 64) {
        g_embsumT[b * 512 + t] = 0.0f;
    } else {
        g_counts[t] = 0.0f;
        float s = 0.0f;
        for (int c = 0; c < CDIM; c++) {
            float v = emb[c * KCODES + t];
            s = __fadd_rn(s, __fmul_rn(v, v));
        }
        g_e2[t] = s;
        if (t == 0) g_diff = 0.0f;
        if (t == 1) g_nflag = 0;
    }
}

// ------------------------- kernel 0b: codebook limb split ------------------
__global__ void k_bsplit(const float* __restrict__ emb) {
    int idx = blockIdx.x * 512 + threadIdx.x;   // 64 x 512
    int n = idx & 511, c = idx >> 9;
    float x = emb[c * KCODES + n];
    __nv_bfloat16 h = __float2bfloat16_rn(x);
    float r = __fsub_rn(x, __bfloat162float(h));
    __nv_bfloat16 m = __float2bfloat16_rn(r);
    float r2 = __fsub_rn(r, __bfloat162float(m));
    __nv_bfloat16 l = __float2bfloat16_rn(r2);
    uint32_t off = (uint32_t)n * 128 + (uint32_t)c * 2;
    *(__nv_bfloat16*)&g_bimg[0][off] = h;
    *(__nv_bfloat16*)&g_bimg[1][off] = m;
    *(__nv_bfloat16*)&g_bimg[2][off] = l;
}

// ------------------------- kernel 1: mma.sync argmin -----------------------
// 2048 CTAs x 256 thr (8 warps). Tile 128 pts x 512 codes, K=64.
// SMEM rows padded to 144B (conflict-free ldmatrix).
#define SA_L    18432                 // per-limb A: 128 * 144
#define SB_BASE 55296                 // 3 * SA_L
#define SB_L    9216                  // per-limb B chunk: 64 * 144
#define SX2     82944                 // SB_BASE + 3*SB_L
#define SE2     83456
#define SM_SZ   85504

__global__ void __launch_bounds__(256) k_mma_argmin(const float* __restrict__ in) {
    extern __shared__ __align__(16) unsigned char sm[];
    const uint32_t sb = s2u(sm);
    float* x2S = (float*)(sm + SX2);
    float* e2S = (float*)(sm + SE2);

    const int tid  = threadIdx.x;
    const int w    = tid >> 5;
    const int lane = tid & 31;
    const int n0   = blockIdx.x * 128;
    const int b    = n0 >> 12;
    const int hw0  = n0 & 4095;
    const float* inb = in + (size_t)b * CDIM * HWSZ + hw0;

    // ---- stage A limbs (padded rows), x2, e2 ----
    for (int idx = tid; idx < 8192; idx += 256) {
        int c = idx >> 7, r = idx & 127;
        float x = __ldg(&inb[(size_t)c * HWSZ + r]);
        __nv_bfloat16 h = __float2bfloat16_rn(x);
        float rr = __fsub_rn(x, __bfloat162float(h));
        __nv_bfloat16 m = __float2bfloat16_rn(rr);
        float rr2 = __fsub_rn(rr, __bfloat162float(m));
        __nv_bfloat16 l = __float2bfloat16_rn(rr2);
        uint32_t o = (uint32_t)r * 144 + (uint32_t)c * 2;
        *(__nv_bfloat16*)&sm[o]            = h;
        *(__nv_bfloat16*)&sm[SA_L + o]     = m;
        *(__nv_bfloat16*)&sm[2 * SA_L + o] = l;
    }
    if (tid < 128) {
        float s = 0.0f;
        for (int c = 0; c < CDIM; c++) {
            float v = __ldg(&inb[(size_t)c * HWSZ + tid]);
            s = __fadd_rn(s, __fmul_rn(v, v));
        }
        x2S[tid] = s;
    }
    e2S[tid]       = g_e2[tid];
    e2S[tid + 256] = g_e2[tid + 256];

    // lane-dependent ldmatrix addresses
    const uint32_t aRow   = (uint32_t)(w * 16 + (lane & 15));
    const uint32_t aBase  = sb + aRow * 144 + ((lane >> 4) << 4);
    const uint32_t bRow   = (uint32_t)((lane & 7) + ((lane >> 4) << 3));
    const uint32_t bBase  = sb + SB_BASE + bRow * 144 + (((lane >> 3) & 1) << 4);

    const int g  = lane >> 2;           // row within warp strip (0..7)
    const int cB = (lane & 3) << 1;     // col pair base within n-tile
    float best0 = 3.4e38f, b20 = 3.4e38f;   // row g
    float best1 = 3.4e38f, b21 = 3.4e38f;   // row g+8
    int bk0 = 0, bk1 = 0;

    for (int ch = 0; ch < 8; ch++) {
        __syncthreads();
        // stage B chunk: 3 limbs x 64 rows x 128B
        for (int t = tid; t < 1536; t += 256) {
            int lb = t >> 9, rem = t & 511, row = rem >> 3, q = rem & 7;
            *(uint4*)&sm[SB_BASE + lb * SB_L + row * 144 + q * 16] =
                *(const uint4*)&g_bimg[lb][(ch * 64 + row) * 128 + q * 16];
        }
        __syncthreads();

        float acc[8][4];
#pragma unroll
        for (int j = 0; j < 8; j++)
#pragma unroll
            for (int q = 0; q < 4; q++) acc[j][q] = 0.0f;

#pragma unroll
        for (int kk = 0; kk < 4; kk++) {
            uint32_t a[3][4];
#pragma unroll
            for (int la = 0; la < 3; la++)
                ldsm4(a[la][0], a[la][1], a[la][2], a[la][3],
                      aBase + la * SA_L + kk * 32);
#pragma unroll
            for (int lb = 0; lb < 3; lb++) {
                uint32_t br[4][4];
#pragma unroll
                for (int j = 0; j < 4; j++)
                    ldsm4(br[j][0], br[j][1], br[j][2], br[j][3],
                          bBase + lb * SB_L + j * (16 * 144) + kk * 32);
                const int nla = 3 - lb;     // lb=0:{h,m,l} lb=1:{h,m} lb=2:{h}
#pragma unroll
                for (int la = 0; la < 3; la++) {
                    if (la < nla) {
#pragma unroll
                        for (int j = 0; j < 4; j++) {
                            mma16816(acc[2 * j],     a[la], br[j][0], br[j][1]);
                            mma16816(acc[2 * j + 1], a[la], br[j][2], br[j][3]);
                        }
                    }
                }
            }
        }

        // epilogue: dist + best/second-best (k ascending)
        float x2a = x2S[w * 16 + g];
        float x2b = x2S[w * 16 + g + 8];
#pragma unroll
        for (int j = 0; j < 8; j++) {
            int kbase = ch * 64 + j * 8 + cB;
#pragma unroll
            for (int e = 0; e < 2; e++) {
                int k = kbase + e;
                float e2 = e2S[k];
                float va = __fadd_rn(__fsub_rn(x2a, __fmul_rn(2.0f, acc[j][e])), e2);
                float vb = __fadd_rn(__fsub_rn(x2b, __fmul_rn(2.0f, acc[j][2 + e])), e2);
                if (va < best0) { b20 = best0; best0 = va; bk0 = k; }
                else if (va < b20) b20 = va;
                if (vb < best1) { b21 = best1; best1 = vb; bk1 = k; }
                else if (vb < b21) b21 = vb;
            }
        }
    }

    // merge across the 4 lanes sharing each row (keep top-2 + index tiebreak)
#pragma unroll
    for (int off = 1; off <= 2; off <<= 1) {
        float vb  = __shfl_xor_sync(0xffffffffu, best0, off);
        float sb2 = __shfl_xor_sync(0xffffffffu, b20, off);
        int   kb  = __shfl_xor_sync(0xffffffffu, bk0, off);
        float nb2 = fminf(fminf(b20, sb2), fmaxf(best0, vb));
        if (vb < best0 || (vb == best0 && kb < bk0)) { best0 = vb; bk0 = kb; }
        b20 = nb2;

        vb  = __shfl_xor_sync(0xffffffffu, best1, off);
        sb2 = __shfl_xor_sync(0xffffffffu, b21, off);
        kb  = __shfl_xor_sync(0xffffffffu, bk1, off);
        nb2 = fminf(fminf(b21, sb2), fmaxf(best1, vb));
        if (vb < best1 || (vb == best1 && kb < bk1)) { best1 = vb; bk1 = kb; }
        b21 = nb2;
    }

    if ((lane & 3) == 0) {
        int p0 = n0 + w * 16 + g;
        g_ind[p0] = bk0;
        g_ind[p0 + 8] = bk1;
        if (__fsub_rn(b20, best0) < MARGIN) {
            int s = atomicAdd(&g_nflag, 1);
            g_flaglist[s] = p0;
        }
        if (__fsub_rn(b21, best1) < MARGIN) {
            int s = atomicAdd(&g_nflag, 1);
            g_flaglist[s] = p0 + 8;
        }
    }
}

// ------------------------- kernel 1b: exact fp32 refine --------------------
__global__ void __launch_bounds__(256) k_refine(const float* __restrict__ in,
                                                const float* __restrict__ emb) {
    __shared__ float xS[64];
    __shared__ float vS[256];
    __shared__ int   kS[256];
    const int tid = threadIdx.x;
    const int cnt = g_nflag;

    for (int i = blockIdx.x; i < cnt; i += gridDim.x) {
        int p = g_flaglist[i];
        int b = p >> 12, hw = p & 4095;
        if (tid < 64)
            xS[tid] = in[(size_t)(b * 64 + tid) * HWSZ + hw];
        __syncthreads();

        float x2 = 0.0f;
        for (int c = 0; c < CDIM; c++)
            x2 = __fadd_rn(x2, __fmul_rn(xS[c], xS[c]));

        float bestv = 3.4e38f;
        int   bestk = 0;
#pragma unroll
        for (int half = 0; half < 2; half++) {
            int k = tid + half * 256;
            float dot = 0.0f;
            for (int c = 0; c < CDIM; c++)
                dot = __fmaf_rn(xS[c], __ldg(&emb[c * KCODES + k]), dot);
            float v = __fadd_rn(__fsub_rn(x2, __fmul_rn(2.0f, dot)), __ldg(&g_e2[k]));
            if (v < bestv) { bestv = v; bestk = k; }
        }
        vS[tid] = bestv; kS[tid] = bestk;
        __syncthreads();
        for (int s = 128; s > 0; s >>= 1) {
            if (tid < s) {
                if (vS[tid + s] < vS[tid] ||
                    (vS[tid + s] == vS[tid] && kS[tid + s] < kS[tid])) {
                    vS[tid] = vS[tid + s]; kS[tid] = kS[tid + s];
                }
            }
            __syncthreads();
        }
        if (tid == 0) g_ind[p] = kS[0];
        __syncthreads();
    }
}

// ------------------------- kernel 2: apply (R3, proven) --------------------
__global__ void __launch_bounds__(256) k_apply(const float* __restrict__ in,
                                               const float* __restrict__ emb,
                                               float* __restrict__ outp) {
    __shared__ __align__(16) float embS[16 * KCODES];
    __shared__ float cntS[KCODES];
    __shared__ float red[8];

    const int tid  = threadIdx.x;
    const int base = blockIdx.x * 512;
    const int b    = base >> 12;
    const int hw   = (base & 4095) + 2 * tid;
    const int p0   = base + 2 * tid;

    cntS[tid] = 0.0f;
    cntS[tid + 256] = 0.0f;

    const int2 kk = *(const int2*)&g_ind[p0];
    float dacc = 0.0f;

    for (int cg = 0; cg < 4; cg++) {
        __syncthreads();
        for (int idx = tid; idx < 16 * 128; idx += 256) {
            int c = idx >> 7, j4 = (idx & 127) << 2;
            *(float4*)&embS[c * KCODES + j4] =
                *(const float4*)(emb + (cg * 16 + c) * KCODES + j4);
        }
        __syncthreads();

#pragma unroll
        for (int q = 0; q < 4; q++) {
            float2 xv[4];
#pragma unroll
            for (int cc = 0; cc < 4; cc++) {
                int c = cg * 16 + q * 4 + cc;
                size_t ib = ((size_t)(b * 64 + c)) * HWSZ + hw;
                float2 x = *(const float2*)&in[ib];
                float e0 = embS[(q * 4 + cc) * KCODES + kk.x];
                float e1 = embS[(q * 4 + cc) * KCODES + kk.y];
                float d0 = __fsub_rn(e0, x.x);
                float d1 = __fsub_rn(e1, x.y);
                float2 o = make_float2(__fadd_rn(x.x, d0), __fadd_rn(x.y, d1));
                *(float2*)&outp[OFF_OUT + ib] = o;
                dacc = __fadd_rn(dacc, __fmul_rn(d0, d0));
                dacc = __fadd_rn(dacc, __fmul_rn(d1, d1));
                xv[cc] = x;
            }
            red4(&g_embsumT[kk.x * 64 + cg * 16 + q * 4],
                 xv[0].x, xv[1].x, xv[2].x, xv[3].x);
            red4(&g_embsumT[kk.y * 64 + cg * 16 + q * 4],
                 xv[0].y, xv[1].y, xv[2].y, xv[3].y);
        }
    }

    atomicAdd(&cntS[kk.x], 1.0f);
    atomicAdd(&cntS[kk.y], 1.0f);
    outp[OFF_IND + p0]     = (float)kk.x;
    outp[OFF_IND + p0 + 1] = (float)kk.y;
    __syncthreads();

    float v0 = cntS[tid], v1 = cntS[tid + 256];
    if (v0 != 0.0f) red1(&g_counts[tid], v0);
    if (v1 != 0.0f) red1(&g_counts[tid + 256], v1);

#pragma unroll
    for (int off = 16; off > 0; off >>= 1)
        dacc += __shfl_down_sync(0xffffffffu, dacc, off);
    if ((tid & 31) == 0) red[tid >> 5] = dacc;
    __syncthreads();
    if (tid == 0) {
        float s = 0.0f;
#pragma unroll
        for (int ww = 0; ww < 8; ww++) s += red[ww];
        red1(&g_diff, s);
    }
}

// ------------------------- kernel 3: finalize ------------------------------
__global__ void k_final1(const float* __restrict__ csin,
                         float* __restrict__ outp) {
    __shared__ float redS[512];
    int k = threadIdx.x;
    float ncs = __fadd_rn(__fmul_rn(csin[k], 0.99f), __fmul_rn(0.01f, g_counts[k]));
    outp[OFF_NCS + k] = ncs;
    redS[k] = ncs;
    __syncthreads();
    for (int s = 256; s > 0; s >>= 1) {
        if (k < s) redS[k] += redS[k + s];
        __syncthreads();
    }
    float n = redS[0];
    g_cs[k] = __fmul_rn(__fdiv_rn(__fadd_rn(ncs, 1e-5f),
                                  __fadd_rn(n, 512.0f * 1e-5f)), n);
    if (k == 0) outp[OFF_DIFF] = g_diff * (1.0f / 16777216.0f);
}

__global__ void k_final2(const float* __restrict__ avgin,
                         float* __restrict__ outp) {
    int idx = blockIdx.x * 512 + threadIdx.x;
    int c = idx >> 9, k = idx & 511;
    float a = __fadd_rn(__fmul_rn(avgin[c * KCODES + k], 0.99f),
                        __fmul_rn(0.01f, g_embsumT[k * 64 + c]));
    outp[OFF_AVG + c * KCODES + k] = a;
    outp[OFF_EMB + c * KCODES + k] = __fdiv_rn(a, g_cs[k]);
}

// ------------------------- launcher ----------------------------------------
extern "C" void kernel_launch(void* const* d_in, const int* in_sizes, int n_in,
                              void* d_out, int out_size) {
    const float* input         = (const float*)d_in[0];
    const float* embedding     = (const float*)d_in[1];
    const float* cluster_size  = (const float*)d_in[2];
    const float* embedding_avg = (const float*)d_in[3];
    float* out = (float*)d_out;

    cudaFuncSetAttribute(k_mma_argmin,
                         cudaFuncAttributeMaxDynamicSharedMemorySize, SM_SZ);

    k_init<<<65, 512>>>(embedding);
    k_bsplit<<<64, 512>>>(embedding);
    k_mma_argmin<<<2048, 256, SM_SZ>>>(input);
    k_refine<<<148, 256>>>(input, embedding);
    k_apply<<<512, 256>>>(input, embedding, out);
    k_final1<<<1, 512>>>(cluster_size, out);
    k_final2<<<64, 512>>>(embedding_avg, out);
}

// round 8
// speedup vs baseline: 1.6431x; 1.2762x over previous
#include <cuda_runtime.h>
#include <cuda_bf16.h>
#include <cstdint>

// ---------------------------------------------------------------------------
// VectorQuantization (VQ-VAE EMA), B=64, C=64, H=64, W=64, K=512
// R8 (= R7 resubmit after infra failure): argmin mma.sync with 3
// limb-products (hh,hm,mh) + double-buffered B staging; exact-fp32 refine
// (margin 4e-3) guarantees indices. Apply/finals proven (R3/R6).
// ---------------------------------------------------------------------------

#define N_PTS   262144
#define CDIM    64
#define KCODES  512
#define HWSZ    4096

#define OFF_OUT   0
#define OFF_DIFF  16777216
#define OFF_IND   16777217
#define OFF_EMB   17039361
#define OFF_NCS   17072129
#define OFF_AVG   17072641

#define MARGIN  4e-3f

// ------------------------- device scratch ----------------------------------
__device__ __align__(16) float g_e2[KCODES];
__device__ __align__(16) int   g_ind[N_PTS];
__device__ __align__(16) float g_counts[KCODES];
__device__ __align__(16) float g_embsumT[KCODES * CDIM];   // [k][c]
__device__ __align__(16) float g_cs[KCODES];
__device__ float g_diff;
__device__ int   g_nflag;
__device__ __align__(16) int g_flaglist[N_PTS];
// bf16 limb images of codebook (h, m), row-major [n][c], 128B rows
__device__ __align__(16) unsigned char g_bimg[2][KCODES * 128];

// ------------------------- helpers -----------------------------------------
__device__ __forceinline__ uint32_t s2u(const void* p) {
    uint32_t a;
    asm("{ .reg .u64 t; cvta.to.shared.u64 t, %1; cvt.u32.u64 %0, t; }"
        : "=r"(a) : "l"(p));
    return a;
}
__device__ __forceinline__ void red4(float* p, float a, float b, float c, float d) {
    unsigned long long g = (unsigned long long)__cvta_generic_to_global(p);
    asm volatile("red.global.add.v4.f32 [%0], {%1,%2,%3,%4};"
                 :: "l"(g), "f"(a), "f"(b), "f"(c), "f"(d) : "memory");
}
__device__ __forceinline__ void red1(float* p, float a) {
    unsigned long long g = (unsigned long long)__cvta_generic_to_global(p);
    asm volatile("red.global.add.f32 [%0], %1;" :: "l"(g), "f"(a) : "memory");
}
__device__ __forceinline__ void ldsm4(uint32_t& r0, uint32_t& r1,
                                      uint32_t& r2, uint32_t& r3, uint32_t addr) {
    asm volatile("ldmatrix.sync.aligned.m8n8.x4.shared.b16 {%0,%1,%2,%3}, [%4];"
                 : "=r"(r0), "=r"(r1), "=r"(r2), "=r"(r3) : "r"(addr));
}
__device__ __forceinline__ void mma16816(float* c, const uint32_t* a,
                                         uint32_t b0, uint32_t b1) {
    asm volatile("mma.sync.aligned.m16n8k16.row.col.f32.bf16.bf16.f32 "
                 "{%0,%1,%2,%3}, {%4,%5,%6,%7}, {%8,%9}, {%0,%1,%2,%3};"
                 : "+f"(c[0]), "+f"(c[1]), "+f"(c[2]), "+f"(c[3])
                 : "r"(a[0]), "r"(a[1]), "r"(a[2]), "r"(a[3]), "r"(b0), "r"(b1));
}

// ------------------------- kernel 0: init ----------------------------------
__global__ void k_init(const float* __restrict__ emb) {
    int b = blockIdx.x, t = threadIdx.x;
    if (b < 64) {
        g_embsumT[b * 512 + t] = 0.0f;
    } else {
        g_counts[t] = 0.0f;
        float s = 0.0f;
        for (int c = 0; c < CDIM; c++) {
            float v = emb[c * KCODES + t];
            s = __fadd_rn(s, __fmul_rn(v, v));
        }
        g_e2[t] = s;
        if (t == 0) g_diff = 0.0f;
        if (t == 1) g_nflag = 0;
    }
}

// ------------------------- kernel 0b: codebook limb split ------------------
__global__ void k_bsplit(const float* __restrict__ emb) {
    int idx = blockIdx.x * 512 + threadIdx.x;   // 64 x 512
    int n = idx & 511, c = idx >> 9;
    float x = emb[c * KCODES + n];
    __nv_bfloat16 h = __float2bfloat16_rn(x);
    float r = __fsub_rn(x, __bfloat162float(h));
    __nv_bfloat16 m = __float2bfloat16_rn(r);
    uint32_t off = (uint32_t)n * 128 + (uint32_t)c * 2;
    *(__nv_bfloat16*)&g_bimg[0][off] = h;
    *(__nv_bfloat16*)&g_bimg[1][off] = m;
}

// ------------------------- kernel 1: mma.sync argmin -----------------------
// 2048 CTAs x 256 thr (8 warps). Tile 128 pts x 512 codes, K=64.
// Rows padded to 144B. B double-buffered (2 limbs x 9216 per buffer).
#define SA_L    18432                 // per-limb A: 128 * 144
#define SB_BASE 36864                 // 2 * SA_L
#define SB_L    9216                  // per-limb B chunk: 64 * 144
#define SB_BUF  18432                 // one buffer = 2 limbs
#define SX2     73728                 // SB_BASE + 2*SB_BUF
#define SE2     74240
#define SM_SZ   76288

__global__ void __launch_bounds__(256) k_mma_argmin(const float* __restrict__ in) {
    extern __shared__ __align__(16) unsigned char sm[];
    const uint32_t sb = s2u(sm);
    float* x2S = (float*)(sm + SX2);
    float* e2S = (float*)(sm + SE2);

    const int tid  = threadIdx.x;
    const int w    = tid >> 5;
    const int lane = tid & 31;
    const int n0   = blockIdx.x * 128;
    const int b    = n0 >> 12;
    const int hw0  = n0 & 4095;
    const float* inb = in + (size_t)b * CDIM * HWSZ + hw0;

    // ---- stage A limbs (h, m), x2, e2 ----
    for (int idx = tid; idx < 8192; idx += 256) {
        int c = idx >> 7, r = idx & 127;
        float x = __ldg(&inb[(size_t)c * HWSZ + r]);
        __nv_bfloat16 h = __float2bfloat16_rn(x);
        float rr = __fsub_rn(x, __bfloat162float(h));
        __nv_bfloat16 m = __float2bfloat16_rn(rr);
        uint32_t o = (uint32_t)r * 144 + (uint32_t)c * 2;
        *(__nv_bfloat16*)&sm[o]        = h;
        *(__nv_bfloat16*)&sm[SA_L + o] = m;
    }
    if (tid < 128) {
        float s = 0.0f;
        for (int c = 0; c < CDIM; c++) {
            float v = __ldg(&inb[(size_t)c * HWSZ + tid]);
            s = __fadd_rn(s, __fmul_rn(v, v));
        }
        x2S[tid] = s;
    }
    e2S[tid]       = g_e2[tid];
    e2S[tid + 256] = g_e2[tid + 256];

    // stage B chunk 0 into buffer 0 (4 uint4 per thread)
    {
        #pragma unroll
        for (int i = 0; i < 4; i++) {
            int idx = tid + 256 * i;                 // 0..1023
            int lb = idx >> 9, rem = idx & 511, row = rem >> 3, q = rem & 7;
            *(uint4*)&sm[SB_BASE + lb * SB_L + row * 144 + q * 16] =
                *(const uint4*)&g_bimg[lb][row * 128 + q * 16];
        }
    }
    __syncthreads();

    // lane-dependent ldmatrix addresses
    const uint32_t aRow  = (uint32_t)(w * 16 + (lane & 15));
    const uint32_t aBase = sb + aRow * 144 + ((lane >> 4) << 4);
    const uint32_t bRow  = (uint32_t)((lane & 7) + ((lane >> 4) << 3));
    const uint32_t bOffL = bRow * 144 + (((lane >> 3) & 1) << 4);

    const int g  = lane >> 2;
    const int cB = (lane & 3) << 1;
    float best0 = 3.4e38f, b20 = 3.4e38f;
    float best1 = 3.4e38f, b21 = 3.4e38f;
    int bk0 = 0, bk1 = 0;

    // per-thread staging source/dest indices (fixed across chunks)
    int s_lb[4], s_row[4], s_q[4];
    #pragma unroll
    for (int i = 0; i < 4; i++) {
        int idx = tid + 256 * i;
        s_lb[i] = idx >> 9; s_row[i] = (idx & 511) >> 3; s_q[i] = idx & 7;
    }

    for (int ch = 0; ch < 8; ch++) {
        const int cur = ch & 1;
        const uint32_t bBase = sb + SB_BASE + cur * SB_BUF + bOffL;

        // prefetch next chunk (LDG only; STS after compute)
        uint4 pf[4];
        if (ch < 7) {
            #pragma unroll
            for (int i = 0; i < 4; i++)
                pf[i] = *(const uint4*)&g_bimg[s_lb[i]]
                            [((ch + 1) * 64 + s_row[i]) * 128 + s_q[i] * 16];
        }

        float acc[8][4];
#pragma unroll
        for (int j = 0; j < 8; j++)
#pragma unroll
            for (int q = 0; q < 4; q++) acc[j][q] = 0.0f;

#pragma unroll
        for (int kk = 0; kk < 4; kk++) {
            uint32_t ah[4], am[4];
            ldsm4(ah[0], ah[1], ah[2], ah[3], aBase + kk * 32);
            ldsm4(am[0], am[1], am[2], am[3], aBase + SA_L + kk * 32);
            uint32_t bh[4][4], bm[4][4];
#pragma unroll
            for (int j = 0; j < 4; j++) {
                ldsm4(bh[j][0], bh[j][1], bh[j][2], bh[j][3],
                      bBase + j * (16 * 144) + kk * 32);
                ldsm4(bm[j][0], bm[j][1], bm[j][2], bm[j][3],
                      bBase + SB_L + j * (16 * 144) + kk * 32);
            }
#pragma unroll
            for (int j = 0; j < 4; j++) {
                mma16816(acc[2 * j],     ah, bh[j][0], bh[j][1]);   // hh
                mma16816(acc[2 * j + 1], ah, bh[j][2], bh[j][3]);
                mma16816(acc[2 * j],     ah, bm[j][0], bm[j][1]);   // hm
                mma16816(acc[2 * j + 1], ah, bm[j][2], bm[j][3]);
                mma16816(acc[2 * j],     am, bh[j][0], bh[j][1]);   // mh
                mma16816(acc[2 * j + 1], am, bh[j][2], bh[j][3]);
            }
        }

        // store prefetched chunk into the other buffer
        if (ch < 7) {
            const uint32_t dst = (uint32_t)(SB_BASE + (1 - cur) * SB_BUF);
            #pragma unroll
            for (int i = 0; i < 4; i++)
                *(uint4*)&sm[dst + s_lb[i] * SB_L + s_row[i] * 144 + s_q[i] * 16]
                    = pf[i];
        }

        // epilogue: dist + best/second-best (k ascending)
        float x2a = x2S[w * 16 + g];
        float x2b = x2S[w * 16 + g + 8];
#pragma unroll
        for (int j = 0; j < 8; j++) {
            int kbase = ch * 64 + j * 8 + cB;
#pragma unroll
            for (int e = 0; e < 2; e++) {
                int k = kbase + e;
                float e2 = e2S[k];
                float va = __fadd_rn(__fsub_rn(x2a, __fmul_rn(2.0f, acc[j][e])), e2);
                float vb = __fadd_rn(__fsub_rn(x2b, __fmul_rn(2.0f, acc[j][2 + e])), e2);
                if (va < best0) { b20 = best0; best0 = va; bk0 = k; }
                else if (va < b20) b20 = va;
                if (vb < best1) { b21 = best1; best1 = vb; bk1 = k; }
                else if (vb < b21) b21 = vb;
            }
        }
        __syncthreads();
    }

    // merge across the 4 lanes sharing each row (top-2 + index tiebreak)
#pragma unroll
    for (int off = 1; off <= 2; off <<= 1) {
        float vb  = __shfl_xor_sync(0xffffffffu, best0, off);
        float sb2 = __shfl_xor_sync(0xffffffffu, b20, off);
        int   kb  = __shfl_xor_sync(0xffffffffu, bk0, off);
        float nb2 = fminf(fminf(b20, sb2), fmaxf(best0, vb));
        if (vb < best0 || (vb == best0 && kb < bk0)) { best0 = vb; bk0 = kb; }
        b20 = nb2;

        vb  = __shfl_xor_sync(0xffffffffu, best1, off);
        sb2 = __shfl_xor_sync(0xffffffffu, b21, off);
        kb  = __shfl_xor_sync(0xffffffffu, bk1, off);
        nb2 = fminf(fminf(b21, sb2), fmaxf(best1, vb));
        if (vb < best1 || (vb == best1 && kb < bk1)) { best1 = vb; bk1 = kb; }
        b21 = nb2;
    }

    if ((lane & 3) == 0) {
        int p0 = n0 + w * 16 + g;
        g_ind[p0] = bk0;
        g_ind[p0 + 8] = bk1;
        if (__fsub_rn(b20, best0) < MARGIN) {
            int s = atomicAdd(&g_nflag, 1);
            g_flaglist[s] = p0;
        }
        if (__fsub_rn(b21, best1) < MARGIN) {
            int s = atomicAdd(&g_nflag, 1);
            g_flaglist[s] = p0 + 8;
        }
    }
}

// ------------------------- kernel 1b: exact fp32 refine --------------------
__global__ void __launch_bounds__(256) k_refine(const float* __restrict__ in,
                                                const float* __restrict__ emb) {
    __shared__ float xS[64];
    __shared__ float vS[256];
    __shared__ int   kS[256];
    const int tid = threadIdx.x;
    const int cnt = g_nflag;

    for (int i = blockIdx.x; i < cnt; i += gridDim.x) {
        int p = g_flaglist[i];
        int b = p >> 12, hw = p & 4095;
        if (tid < 64)
            xS[tid] = in[(size_t)(b * 64 + tid) * HWSZ + hw];
        __syncthreads();

        float x2 = 0.0f;
        for (int c = 0; c < CDIM; c++)
            x2 = __fadd_rn(x2, __fmul_rn(xS[c], xS[c]));

        float bestv = 3.4e38f;
        int   bestk = 0;
#pragma unroll
        for (int half = 0; half < 2; half++) {
            int k = tid + half * 256;
            float dot = 0.0f;
            for (int c = 0; c < CDIM; c++)
                dot = __fmaf_rn(xS[c], __ldg(&emb[c * KCODES + k]), dot);
            float v = __fadd_rn(__fsub_rn(x2, __fmul_rn(2.0f, dot)), __ldg(&g_e2[k]));
            if (v < bestv) { bestv = v; bestk = k; }
        }
        vS[tid] = bestv; kS[tid] = bestk;
        __syncthreads();
        for (int s = 128; s > 0; s >>= 1) {
            if (tid < s) {
                if (vS[tid + s] < vS[tid] ||
                    (vS[tid + s] == vS[tid] && kS[tid + s] < kS[tid])) {
                    vS[tid] = vS[tid + s]; kS[tid] = kS[tid + s];
                }
            }
            __syncthreads();
        }
        if (tid == 0) g_ind[p] = kS[0];
        __syncthreads();
    }
}

// ------------------------- kernel 2: apply (proven) ------------------------
__global__ void __launch_bounds__(256) k_apply(const float* __restrict__ in,
                                               const float* __restrict__ emb,
                                               float* __restrict__ outp) {
    __shared__ __align__(16) float embS[16 * KCODES];
    __shared__ float cntS[KCODES];
    __shared__ float red[8];

    const int tid  = threadIdx.x;
    const int base = blockIdx.x * 512;
    const int b    = base >> 12;
    const int hw   = (base & 4095) + 2 * tid;
    const int p0   = base + 2 * tid;

    cntS[tid] = 0.0f;
    cntS[tid + 256] = 0.0f;

    const int2 kk = *(const int2*)&g_ind[p0];
    float dacc = 0.0f;

    for (int cg = 0; cg < 4; cg++) {
        __syncthreads();
        for (int idx = tid; idx < 16 * 128; idx += 256) {
            int c = idx >> 7, j4 = (idx & 127) << 2;
            *(float4*)&embS[c * KCODES + j4] =
                *(const float4*)(emb + (cg * 16 + c) * KCODES + j4);
        }
        __syncthreads();

#pragma unroll
        for (int q = 0; q < 4; q++) {
            float2 xv[4];
#pragma unroll
            for (int cc = 0; cc < 4; cc++) {
                int c = cg * 16 + q * 4 + cc;
                size_t ib = ((size_t)(b * 64 + c)) * HWSZ + hw;
                float2 x = *(const float2*)&in[ib];
                float e0 = embS[(q * 4 + cc) * KCODES + kk.x];
                float e1 = embS[(q * 4 + cc) * KCODES + kk.y];
                float d0 = __fsub_rn(e0, x.x);
                float d1 = __fsub_rn(e1, x.y);
                float2 o = make_float2(__fadd_rn(x.x, d0), __fadd_rn(x.y, d1));
                *(float2*)&outp[OFF_OUT + ib] = o;
                dacc = __fadd_rn(dacc, __fmul_rn(d0, d0));
                dacc = __fadd_rn(dacc, __fmul_rn(d1, d1));
                xv[cc] = x;
            }
            red4(&g_embsumT[kk.x * 64 + cg * 16 + q * 4],
                 xv[0].x, xv[1].x, xv[2].x, xv[3].x);
            red4(&g_embsumT[kk.y * 64 + cg * 16 + q * 4],
                 xv[0].y, xv[1].y, xv[2].y, xv[3].y);
        }
    }

    atomicAdd(&cntS[kk.x], 1.0f);
    atomicAdd(&cntS[kk.y], 1.0f);
    outp[OFF_IND + p0]     = (float)kk.x;
    outp[OFF_IND + p0 + 1] = (float)kk.y;
    __syncthreads();

    float v0 = cntS[tid], v1 = cntS[tid + 256];
    if (v0 != 0.0f) red1(&g_counts[tid], v0);
    if (v1 != 0.0f) red1(&g_counts[tid + 256], v1);

#pragma unroll
    for (int off = 16; off > 0; off >>= 1)
        dacc += __shfl_down_sync(0xffffffffu, dacc, off);
    if ((tid & 31) == 0) red[tid >> 5] = dacc;
    __syncthreads();
    if (tid == 0) {
        float s = 0.0f;
#pragma unroll
        for (int ww = 0; ww < 8; ww++) s += red[ww];
        red1(&g_diff, s);
    }
}

// ------------------------- kernel 3: finalize ------------------------------
__global__ void k_final1(const float* __restrict__ csin,
                         float* __restrict__ outp) {
    __shared__ float redS[512];
    int k = threadIdx.x;
    float ncs = __fadd_rn(__fmul_rn(csin[k], 0.99f), __fmul_rn(0.01f, g_counts[k]));
    outp[OFF_NCS + k] = ncs;
    redS[k] = ncs;
    __syncthreads();
    for (int s = 256; s > 0; s >>= 1) {
        if (k < s) redS[k] += redS[k + s];
        __syncthreads();
    }
    float n = redS[0];
    g_cs[k] = __fmul_rn(__fdiv_rn(__fadd_rn(ncs, 1e-5f),
                                  __fadd_rn(n, 512.0f * 1e-5f)), n);
    if (k == 0) outp[OFF_DIFF] = g_diff * (1.0f / 16777216.0f);
}

__global__ void k_final2(const float* __restrict__ avgin,
                         float* __restrict__ outp) {
    int idx = blockIdx.x * 512 + threadIdx.x;
    int c = idx >> 9, k = idx & 511;
    float a = __fadd_rn(__fmul_rn(avgin[c * KCODES + k], 0.99f),
                        __fmul_rn(0.01f, g_embsumT[k * 64 + c]));
    outp[OFF_AVG + c * KCODES + k] = a;
    outp[OFF_EMB + c * KCODES + k] = __fdiv_rn(a, g_cs[k]);
}

// ------------------------- launcher ----------------------------------------
extern "C" void kernel_launch(void* const* d_in, const int* in_sizes, int n_in,
                              void* d_out, int out_size) {
    const float* input         = (const float*)d_in[0];
    const float* embedding     = (const float*)d_in[1];
    const float* cluster_size  = (const float*)d_in[2];
    const float* embedding_avg = (const float*)d_in[3];
    float* out = (float*)d_out;

    cudaFuncSetAttribute(k_mma_argmin,
                         cudaFuncAttributeMaxDynamicSharedMemorySize, SM_SZ);

    k_init<<<65, 512>>>(embedding);
    k_bsplit<<<64, 512>>>(embedding);
    k_mma_argmin<<<2048, 256, SM_SZ>>>(input);
    k_refine<<<148, 256>>>(input, embedding);
    k_apply<<<512, 256>>>(input, embedding, out);
    k_final1<<<1, 512>>>(cluster_size, out);
    k_final2<<<64, 512>>>(embedding_avg, out);
}

// round 11
// speedup vs baseline: 2.0849x; 1.2689x over previous
#include <cuda_runtime.h>
#include <cuda_bf16.h>
#include <cstdint>

// ---------------------------------------------------------------------------
// VectorQuantization (VQ-VAE EMA), B=64, C=64, H=64, W=64, K=512
// R11 (= R9 resubmit; 2 prior attempts hit infra container failures):
// single fused kernel (limb stage -> mma.sync argmin -> in-CTA exact
// refine -> apply with x~ = h+m). g_embT fp32 [k][c] for row gathers.
// ---------------------------------------------------------------------------

#define N_PTS   262144
#define CDIM    64
#define KCODES  512
#define HWSZ    4096

#define OFF_OUT   0
#define OFF_DIFF  16777216
#define OFF_IND   16777217
#define OFF_EMB   17039361
#define OFF_NCS   17072129
#define OFF_AVG   17072641

#define MARGIN  4e-3f

// ------------------------- device scratch ----------------------------------
__device__ __align__(16) float g_e2[KCODES];
__device__ __align__(16) float g_counts[KCODES];
__device__ __align__(16) float g_embsumT[KCODES * CDIM];   // [k][c]
__device__ __align__(16) float g_embT[KCODES * CDIM];      // fp32 [k][c]
__device__ __align__(16) float g_cs[KCODES];
__device__ float g_diff;
// bf16 limb images of codebook (h, m), row-major [n][c], 128B rows
__device__ __align__(16) unsigned char g_bimg[2][KCODES * 128];

// ------------------------- helpers -----------------------------------------
__device__ __forceinline__ uint32_t s2u(const void* p) {
    uint32_t a;
    asm("{ .reg .u64 t; cvta.to.shared.u64 t, %1; cvt.u32.u64 %0, t; }"
        : "=r"(a) : "l"(p));
    return a;
}
__device__ __forceinline__ void red4(float* p, float a, float b, float c, float d) {
    unsigned long long g = (unsigned long long)__cvta_generic_to_global(p);
    asm volatile("red.global.add.v4.f32 [%0], {%1,%2,%3,%4};"
                 :: "l"(g), "f"(a), "f"(b), "f"(c), "f"(d) : "memory");
}
__device__ __forceinline__ void red1(float* p, float a) {
    unsigned long long g = (unsigned long long)__cvta_generic_to_global(p);
    asm volatile("red.global.add.f32 [%0], %1;" :: "l"(g), "f"(a) : "memory");
}
__device__ __forceinline__ void ldsm4(uint32_t& r0, uint32_t& r1,
                                      uint32_t& r2, uint32_t& r3, uint32_t addr) {
    asm volatile("ldmatrix.sync.aligned.m8n8.x4.shared.b16 {%0,%1,%2,%3}, [%4];"
                 : "=r"(r0), "=r"(r1), "=r"(r2), "=r"(r3) : "r"(addr));
}
__device__ __forceinline__ void mma16816(float* c, const uint32_t* a,
                                         uint32_t b0, uint32_t b1) {
    asm volatile("mma.sync.aligned.m16n8k16.row.col.f32.bf16.bf16.f32 "
                 "{%0,%1,%2,%3}, {%4,%5,%6,%7}, {%8,%9}, {%0,%1,%2,%3};"
                 : "+f"(c[0]), "+f"(c[1]), "+f"(c[2]), "+f"(c[3])
                 : "r"(a[0]), "r"(a[1]), "r"(a[2]), "r"(a[3]), "r"(b0), "r"(b1));
}

// ------------------------- kernel 0: prep ----------------------------------
__global__ void k_prep(const float* __restrict__ emb) {
    int blk = blockIdx.x, t = threadIdx.x;
    if (blk < 64) {
        g_embsumT[blk * 512 + t] = 0.0f;
    } else if (blk == 64) {
        g_counts[t] = 0.0f;
        float s = 0.0f;
        for (int c = 0; c < CDIM; c++) {
            float v = emb[c * KCODES + t];
            s = __fadd_rn(s, __fmul_rn(v, v));
        }
        g_e2[t] = s;
        if (t == 0) g_diff = 0.0f;
    } else {
        int idx = (blk - 65) * 512 + t;     // 0..32767
        int n = idx & 511, c = idx >> 9;
        float x = emb[c * KCODES + n];
        __nv_bfloat16 h = __float2bfloat16_rn(x);
        float r = __fsub_rn(x, __bfloat162float(h));
        __nv_bfloat16 m = __float2bfloat16_rn(r);
        uint32_t off = (uint32_t)n * 128 + (uint32_t)c * 2;
        *(__nv_bfloat16*)&g_bimg[0][off] = h;
        *(__nv_bfloat16*)&g_bimg[1][off] = m;
        g_embT[n * 64 + c] = x;
    }
}

// ------------------------- fused kernel ------------------------------------
// SMEM layout
#define SA0     0                     // h limb A: 128*144
#define SA1     18432                 // m limb A
#define SB_BASE 36864                 // B double buffer 2*18432 -> 73728
#define SB_L    9216
#define SB_BUF  18432
#define SE2     73728                 // 512 f -> 75776
#define SKS     75776                 // 128 int -> 76288
#define SFLG    76288                 // 128 bytes -> 76416
#define SRED    76416                 // 8 f -> 76448
#define SM_SZ   76480
// phase C/D scratch inside B-buffer area (free after MMA):
#define SCNT    SB_BASE               // 512 f hist
#define SXS     (SB_BASE + 2048)      // 64 f
#define SVS     (SB_BASE + 2304)      // 256 f
#define SKR     (SB_BASE + 3328)      // 256 int

__global__ void __launch_bounds__(256) k_fused(const float* __restrict__ in,
                                               float* __restrict__ outp) {
    extern __shared__ __align__(16) unsigned char sm[];
    const uint32_t sb = s2u(sm);
    float* e2S   = (float*)(sm + SE2);
    int*   kS    = (int*)(sm + SKS);
    unsigned char* flagS = sm + SFLG;
    float* redS  = (float*)(sm + SRED);

    const int tid  = threadIdx.x;
    const int w    = tid >> 5;
    const int lane = tid & 31;
    const int n0   = blockIdx.x * 128;
    const int b    = n0 >> 12;
    const int hw0  = n0 & 4095;
    const float* inb = in + (size_t)b * CDIM * HWSZ + hw0;

    // ---------------- Phase A: stage limbs, e2, B chunk 0 ----------------
    for (int idx = tid; idx < 8192; idx += 256) {
        int c = idx >> 7, r = idx & 127;
        float x = __ldg(&inb[(size_t)c * HWSZ + r]);
        __nv_bfloat16 h = __float2bfloat16_rn(x);
        float rr = __fsub_rn(x, __bfloat162float(h));
        __nv_bfloat16 m = __float2bfloat16_rn(rr);
        uint32_t o = (uint32_t)r * 144 + (uint32_t)c * 2;
        *(__nv_bfloat16*)&sm[SA0 + o] = h;
        *(__nv_bfloat16*)&sm[SA1 + o] = m;
    }
    e2S[tid]       = g_e2[tid];
    e2S[tid + 256] = g_e2[tid + 256];
    if (tid < 128) flagS[tid] = 0;

    int s_lb[4], s_row[4], s_q[4];
#pragma unroll
    for (int i = 0; i < 4; i++) {
        int idx = tid + 256 * i;
        s_lb[i] = idx >> 9; s_row[i] = (idx & 511) >> 3; s_q[i] = idx & 7;
    }
#pragma unroll
    for (int i = 0; i < 4; i++)
        *(uint4*)&sm[SB_BASE + s_lb[i] * SB_L + s_row[i] * 144 + s_q[i] * 16] =
            *(const uint4*)&g_bimg[s_lb[i]][s_row[i] * 128 + s_q[i] * 16];
    __syncthreads();

    // ---------------- Phase B: MMA argmin --------------------------------
    const uint32_t aRow  = (uint32_t)(w * 16 + (lane & 15));
    const uint32_t aBase = sb + aRow * 144 + ((lane >> 4) << 4);
    const uint32_t bRow  = (uint32_t)((lane & 7) + ((lane >> 4) << 3));
    const uint32_t bOffL = bRow * 144 + (((lane >> 3) & 1) << 4);

    const int g  = lane >> 2;
    const int cB = (lane & 3) << 1;
    float best0 = 3.4e38f, b20 = 3.4e38f;
    float best1 = 3.4e38f, b21 = 3.4e38f;
    int bk0 = 0, bk1 = 0;

    for (int ch = 0; ch < 8; ch++) {
        const int cur = ch & 1;
        const uint32_t bBase = sb + SB_BASE + cur * SB_BUF + bOffL;

        uint4 pf[4];
        if (ch < 7) {
#pragma unroll
            for (int i = 0; i < 4; i++)
                pf[i] = *(const uint4*)&g_bimg[s_lb[i]]
                            [((ch + 1) * 64 + s_row[i]) * 128 + s_q[i] * 16];
        }

        float acc[8][4];
#pragma unroll
        for (int j = 0; j < 8; j++)
#pragma unroll
            for (int q = 0; q < 4; q++) acc[j][q] = 0.0f;

#pragma unroll
        for (int kk = 0; kk < 4; kk++) {
            uint32_t ah[4], am[4];
            ldsm4(ah[0], ah[1], ah[2], ah[3], aBase + kk * 32);
            ldsm4(am[0], am[1], am[2], am[3], aBase + SA1 + kk * 32);
            uint32_t bh[4][4], bm[4][4];
#pragma unroll
            for (int j = 0; j < 4; j++) {
                ldsm4(bh[j][0], bh[j][1], bh[j][2], bh[j][3],
                      bBase + j * (16 * 144) + kk * 32);
                ldsm4(bm[j][0], bm[j][1], bm[j][2], bm[j][3],
                      bBase + SB_L + j * (16 * 144) + kk * 32);
            }
#pragma unroll
            for (int j = 0; j < 4; j++) {
                mma16816(acc[2 * j],     ah, bh[j][0], bh[j][1]);   // hh
                mma16816(acc[2 * j + 1], ah, bh[j][2], bh[j][3]);
                mma16816(acc[2 * j],     ah, bm[j][0], bm[j][1]);   // hm
                mma16816(acc[2 * j + 1], ah, bm[j][2], bm[j][3]);
                mma16816(acc[2 * j],     am, bh[j][0], bh[j][1]);   // mh
                mma16816(acc[2 * j + 1], am, bh[j][2], bh[j][3]);
            }
        }

        if (ch < 7) {
            const uint32_t dst = (uint32_t)(SB_BASE + (1 - cur) * SB_BUF);
#pragma unroll
            for (int i = 0; i < 4; i++)
                *(uint4*)&sm[dst + s_lb[i] * SB_L + s_row[i] * 144 + s_q[i] * 16]
                    = pf[i];
        }

        // epilogue: v = e2 - 2*dot (x2 constant per point, dropped)
#pragma unroll
        for (int j = 0; j < 8; j++) {
            int kbase = ch * 64 + j * 8 + cB;
#pragma unroll
            for (int e = 0; e < 2; e++) {
                int k = kbase + e;
                float e2 = e2S[k];
                float va = __fmaf_rn(acc[j][e],     -2.0f, e2);
                float vb = __fmaf_rn(acc[j][2 + e], -2.0f, e2);
                if (va < best0) { b20 = best0; best0 = va; bk0 = k; }
                else if (va < b20) b20 = va;
                if (vb < best1) { b21 = best1; best1 = vb; bk1 = k; }
                else if (vb < b21) b21 = vb;
            }
        }
        __syncthreads();
    }

    // merge across the 4 lanes per row (top-2 + first-index tiebreak)
#pragma unroll
    for (int off = 1; off <= 2; off <<= 1) {
        float vb  = __shfl_xor_sync(0xffffffffu, best0, off);
        float sb2 = __shfl_xor_sync(0xffffffffu, b20, off);
        int   kb  = __shfl_xor_sync(0xffffffffu, bk0, off);
        float nb2 = fminf(fminf(b20, sb2), fmaxf(best0, vb));
        if (vb < best0 || (vb == best0 && kb < bk0)) { best0 = vb; bk0 = kb; }
        b20 = nb2;

        vb  = __shfl_xor_sync(0xffffffffu, best1, off);
        sb2 = __shfl_xor_sync(0xffffffffu, b21, off);
        kb  = __shfl_xor_sync(0xffffffffu, bk1, off);
        nb2 = fminf(fminf(b21, sb2), fmaxf(best1, vb));
        if (vb < best1 || (vb == best1 && kb < bk1)) { best1 = vb; bk1 = kb; }
        b21 = nb2;
    }
    if ((lane & 3) == 0) {
        int i0 = w * 16 + g;
        kS[i0] = bk0;
        kS[i0 + 8] = bk1;
        if (__fsub_rn(b20, best0) < MARGIN) flagS[i0] = 1;
        if (__fsub_rn(b21, best1) < MARGIN) flagS[i0 + 8] = 1;
    }
    __syncthreads();

    // ---------------- Phase C: in-CTA exact fp32 refine ------------------
    float* xS  = (float*)(sm + SXS);
    float* vS  = (float*)(sm + SVS);
    int*   kR  = (int*)(sm + SKR);
    for (int i = 0; i < 128; i++) {
        if (!flagS[i]) continue;
        if (tid < 64)
            xS[tid] = in[(size_t)(b * 64 + tid) * HWSZ + hw0 + i];
        __syncthreads();
        float x2 = 0.0f;
        for (int c = 0; c < CDIM; c++)
            x2 = __fadd_rn(x2, __fmul_rn(xS[c], xS[c]));
        float bestv = 3.4e38f;
        int   bestk = 0;
#pragma unroll
        for (int half = 0; half < 2; half++) {
            int k = tid + half * 256;
            const float* er = &g_embT[k * 64];
            float dot = 0.0f;
            for (int c = 0; c < CDIM; c++)
                dot = __fmaf_rn(xS[c], __ldg(&er[c]), dot);
            float v = __fadd_rn(__fsub_rn(x2, __fmul_rn(2.0f, dot)), e2S[k]);
            if (v < bestv) { bestv = v; bestk = k; }
        }
        vS[tid] = bestv; kR[tid] = bestk;
        __syncthreads();
        for (int s = 128; s > 0; s >>= 1) {
            if (tid < s) {
                if (vS[tid + s] < vS[tid] ||
                    (vS[tid + s] == vS[tid] && kR[tid + s] < kR[tid])) {
                    vS[tid] = vS[tid + s]; kR[tid] = kR[tid + s];
                }
            }
            __syncthreads();
        }
        if (tid == 0) kS[i] = kR[0];
        __syncthreads();
    }
    __syncthreads();

    // ---------------- Phase D: apply -------------------------------------
    float* cntS = (float*)(sm + SCNT);
    cntS[tid] = 0.0f;
    cntS[tid + 256] = 0.0f;
    __syncthreads();

    const int pt    = tid & 127;
    const int chalf = tid >> 7;
    const int c0    = chalf * 32;
    const int myk   = kS[pt];

    if (tid < 128) {
        atomicAdd(&cntS[myk], 1.0f);
        outp[OFF_IND + n0 + tid] = (float)myk;
    }

    const float* erow = &g_embT[myk * 64 + c0];
    const uint32_t lb = (uint32_t)pt * 144 + (uint32_t)c0 * 2;
    float dacc = 0.0f;

#pragma unroll
    for (int q = 0; q < 8; q++) {
        float4 e4 = *(const float4*)(erow + 4 * q);
        uint2 hu = *(const uint2*)&sm[SA0 + lb + 8 * q];
        uint2 mu = *(const uint2*)&sm[SA1 + lb + 8 * q];
        float2 h01 = __bfloat1622float2(*(__nv_bfloat162*)&hu.x);
        float2 h23 = __bfloat1622float2(*(__nv_bfloat162*)&hu.y);
        float2 m01 = __bfloat1622float2(*(__nv_bfloat162*)&mu.x);
        float2 m23 = __bfloat1622float2(*(__nv_bfloat162*)&mu.y);
        float xt0 = __fadd_rn(h01.x, m01.x);
        float xt1 = __fadd_rn(h01.y, m01.y);
        float xt2 = __fadd_rn(h23.x, m23.x);
        float xt3 = __fadd_rn(h23.y, m23.y);
        float d0 = __fsub_rn(e4.x, xt0);
        float d1 = __fsub_rn(e4.y, xt1);
        float d2 = __fsub_rn(e4.z, xt2);
        float d3 = __fsub_rn(e4.w, xt3);
        size_t ob = ((size_t)(b * 64 + c0 + 4 * q)) * HWSZ + hw0 + pt;
        outp[OFF_OUT + ob]            = __fadd_rn(xt0, d0);
        outp[OFF_OUT + ob + HWSZ]     = __fadd_rn(xt1, d1);
        outp[OFF_OUT + ob + 2 * HWSZ] = __fadd_rn(xt2, d2);
        outp[OFF_OUT + ob + 3 * HWSZ] = __fadd_rn(xt3, d3);
        dacc = __fadd_rn(dacc, __fmul_rn(d0, d0));
        dacc = __fadd_rn(dacc, __fmul_rn(d1, d1));
        dacc = __fadd_rn(dacc, __fmul_rn(d2, d2));
        dacc = __fadd_rn(dacc, __fmul_rn(d3, d3));
        red4(&g_embsumT[myk * 64 + c0 + 4 * q], xt0, xt1, xt2, xt3);
    }
    __syncthreads();

    // counts flush
    {
        float v0 = cntS[tid], v1 = cntS[tid + 256];
        if (v0 != 0.0f) red1(&g_counts[tid], v0);
        if (v1 != 0.0f) red1(&g_counts[tid + 256], v1);
    }

    // diff reduction
#pragma unroll
    for (int off = 16; off > 0; off >>= 1)
        dacc += __shfl_down_sync(0xffffffffu, dacc, off);
    if ((tid & 31) == 0) redS[tid >> 5] = dacc;
    __syncthreads();
    if (tid == 0) {
        float s = 0.0f;
#pragma unroll
        for (int ww = 0; ww < 8; ww++) s += redS[ww];
        red1(&g_diff, s);
    }
}

// ------------------------- finals ------------------------------------------
__global__ void k_final1(const float* __restrict__ csin,
                         float* __restrict__ outp) {
    __shared__ float redS[512];
    int k = threadIdx.x;
    float ncs = __fadd_rn(__fmul_rn(csin[k], 0.99f), __fmul_rn(0.01f, g_counts[k]));
    outp[OFF_NCS + k] = ncs;
    redS[k] = ncs;
    __syncthreads();
    for (int s = 256; s > 0; s >>= 1) {
        if (k < s) redS[k] += redS[k + s];
        __syncthreads();
    }
    float n = redS[0];
    g_cs[k] = __fmul_rn(__fdiv_rn(__fadd_rn(ncs, 1e-5f),
                                  __fadd_rn(n, 512.0f * 1e-5f)), n);
    if (k == 0) outp[OFF_DIFF] = g_diff * (1.0f / 16777216.0f);
}

__global__ void k_final2(const float* __restrict__ avgin,
                         float* __restrict__ outp) {
    int idx = blockIdx.x * 512 + threadIdx.x;
    int c = idx >> 9, k = idx & 511;
    float a = __fadd_rn(__fmul_rn(avgin[c * KCODES + k], 0.99f),
                        __fmul_rn(0.01f, g_embsumT[k * 64 + c]));
    outp[OFF_AVG + c * KCODES + k] = a;
    outp[OFF_EMB + c * KCODES + k] = __fdiv_rn(a, g_cs[k]);
}

// ------------------------- launcher ----------------------------------------
extern "C" void kernel_launch(void* const* d_in, const int* in_sizes, int n_in,
                              void* d_out, int out_size) {
    const float* input         = (const float*)d_in[0];
    const float* embedding     = (const float*)d_in[1];
    const float* cluster_size  = (const float*)d_in[2];
    const float* embedding_avg = (const float*)d_in[3];
    float* out = (float*)d_out;

    cudaFuncSetAttribute(k_fused,
                         cudaFuncAttributeMaxDynamicSharedMemorySize, SM_SZ);

    k_prep<<<129, 512>>>(embedding);
    k_fused<<<2048, 256, SM_SZ>>>(input, out);
    k_final1<<<1, 512>>>(cluster_size, out);
    k_final2<<<64, 512>>>(embedding_avg, out);
}